// round 1
// baseline (speedup 1.0000x reference)
#include <cuda_runtime.h>

// QModel_43885975830736
//
// Mathematical identity: wire 8 is never acted on by any gate. The state's
// wire8=1 block is exactly zero throughout (it is initialized to exact zeros
// and every gate acts within wires 0..7, so zeros only ever combine with
// zeros). All gates are unitary and the embedding normalizes the state, so
// probs(wire 8) == [1, 0] for every batch row, independent of x and weights.
// The reference computes this in complex64; its deviation from [1,0] is only
// accumulated rounding in ~48 norm-preserving complex multiplies per
// amplitude, i.e. O(1e-6) on the first column and EXACTLY 0 on the second.
// Well inside the 1e-3 relative-error gate.
//
// Therefore the fastest correct kernel writes the constant pattern
// 1,0,1,0,... into the (BATCH, 2) fp32 output. 128 KB of stores; runtime is
// pure launch overhead.

__global__ void qmodel_const_kernel(float4* __restrict__ out4, int n4,
                                    float* __restrict__ out, int n) {
    int i = blockIdx.x * blockDim.x + threadIdx.x;
    // Vectorized body: each float4 covers two (p0, p1) pairs -> (1,0,1,0).
    if (i < n4) {
        out4[i] = make_float4(1.0f, 0.0f, 1.0f, 0.0f);
    }
    // Scalar tail (only if out_size not divisible by 4).
    int tail_start = n4 * 4;
    int t = tail_start + i;
    if (t < n) {
        out[t] = (t & 1) ? 0.0f : 1.0f;
    }
}

extern "C" void kernel_launch(void* const* d_in, const int* in_sizes, int n_in,
                              void* d_out, int out_size) {
    (void)d_in; (void)in_sizes; (void)n_in;
    float* out = (float*)d_out;
    int n = out_size;          // expected 16384 * 2 = 32768 fp32 elements
    int n4 = n / 4;            // 8192 float4 stores
    int threads = 256;
    int blocks = (n4 + threads - 1) / threads;
    if (blocks < 1) blocks = 1;
    qmodel_const_kernel<<<blocks, threads>>>((float4*)d_out, n4, out, n);
}